// round 3
// baseline (speedup 1.0000x reference)
#include <cuda_runtime.h>
#include <math.h>

#define NB   2
#define NHD  8
#define HD   32
#define CH   256
#define HI   40
#define WIM  40
#define HW   1600
#define WSZ  15
#define WS2  225
#define NEGV 1e8f
#define INV_T 0.17677669529663687f   // 1/sqrt(32)

#define OUT_ELEMS  (HW*NB*CH)            // 819200
#define ATTN_ELEMS (NB*NHD*HW*WS2)       // 5760000

// ---- scratch (no allocations allowed) ----
__device__ float g_qp[NB*NHD*HW*HD];   // [n][h][i][d], unscaled
__device__ float g_kp[NB*NHD*HW*HD];   // [n][h][j][d], scaled by 1/T
__device__ float g_vp[NB*NHD*HW*HD];   // [n][h][j][d]
__device__ float g_ctx[HW*NB*CH];      // [i][n][c] pre-output-projection

// ============================================================
// Kernel 1: fused QKV 1x1-conv projection.
// Y[n][o][p] = sum_c W[o][c] * X[n][c][p] + b[o]  (K scaled by 1/T)
// grid: (p_tiles=25, o_tiles=4, z=6: n = z&1, tensor = z>>1), 256 thr
// ============================================================
__global__ void __launch_bounds__(256) proj_kernel(
    const float* __restrict__ q, const float* __restrict__ k, const float* __restrict__ v,
    const float* __restrict__ Wq, const float* __restrict__ bq,
    const float* __restrict__ Wk, const float* __restrict__ bk,
    const float* __restrict__ Wv, const float* __restrict__ bv)
{
    __shared__ __align__(16) float Ws[64][32];
    __shared__ __align__(16) float Bs[32][64];

    int z = blockIdx.z;
    int n = z & 1, t = z >> 1;
    const float* X; const float* W; const float* b; float* Y; float scale;
    if (t == 0)      { X = q; W = Wq; b = bq; Y = g_qp; scale = 1.0f;  }
    else if (t == 1) { X = k; W = Wk; b = bk; Y = g_kp; scale = INV_T; }
    else             { X = v; W = Wv; b = bv; Y = g_vp; scale = 1.0f;  }
    X += (size_t)n * CH * HW;

    int o0 = blockIdx.y * 64, p0 = blockIdx.x * 64;
    int tid = threadIdx.x;
    int tx = tid & 15, ty = tid >> 4;

    float acc[4][4] = {};

    for (int k0 = 0; k0 < CH; k0 += 32) {
#pragma unroll
        for (int s = 0; s < 8; s++) {
            int idx = tid + s * 256;
            int row = idx >> 5, col = idx & 31;
            Ws[row][col] = W[(size_t)(o0 + row) * CH + k0 + col];
        }
#pragma unroll
        for (int s = 0; s < 8; s++) {
            int idx = tid + s * 256;
            int col = idx & 63, row = idx >> 6;
            Bs[row][col] = X[(size_t)(k0 + row) * HW + p0 + col];
        }
        __syncthreads();
#pragma unroll
        for (int cc = 0; cc < 32; cc++) {
            float4 b4 = *reinterpret_cast<const float4*>(&Bs[cc][tx * 4]);
            float bb[4] = {b4.x, b4.y, b4.z, b4.w};
            float aa[4];
#pragma unroll
            for (int i = 0; i < 4; i++) aa[i] = Ws[ty * 4 + i][cc];
#pragma unroll
            for (int i = 0; i < 4; i++)
#pragma unroll
                for (int j = 0; j < 4; j++)
                    acc[i][j] = fmaf(aa[i], bb[j], acc[i][j]);
        }
        __syncthreads();
    }

#pragma unroll
    for (int i = 0; i < 4; i++) {
        int o = o0 + ty * 4 + i;
        int h = o >> 5, d = o & 31;
        float bias = b[o];
#pragma unroll
        for (int j = 0; j < 4; j++) {
            int p = p0 + tx * 4 + j;
            float val = (acc[i][j] + bias) * scale;
            Y[((size_t)(n * NHD + h) * HW + p) * HD + d] = val;
        }
    }
}

// ============================================================
// Kernel 2: local attention. Block per (qy, h, n). 320 threads.
// smem: sQ[40*32] | sL[40*225] | sA[15*40*32] (K then V) | sR[7200] (relw then relv)
// ============================================================
#define SM_Q   0
#define SM_L   1280
#define SM_A   10280
#define SM_R   29480
#define SM_FLOATS 36680
#define SM_BYTES  (SM_FLOATS * 4)

__global__ void __launch_bounds__(320, 1) attn_kernel(
    const float* __restrict__ relw_g,   // [NHD][WS2][HD]
    const float* __restrict__ relb_g,   // [NHD][WS2]
    const float* __restrict__ relv_g,   // [NHD][HD][WS2]
    float* __restrict__ attn_out)       // may be null
{
    int qy = blockIdx.x, h = blockIdx.y, n = blockIdx.z;
    int tid = threadIdx.x;
    extern __shared__ __align__(16) float sm[];
    float* sQ = sm + SM_Q;
    float* sL = sm + SM_L;
    float* sA = sm + SM_A;
    float* sR = sm + SM_R;

    int nh_base = (n * NHD + h) * HW;

    // ---- stage Q row, K rows (zero-filled OOB), rel_k_w ----
    {
        const float* src = g_qp + (size_t)(nh_base + qy * WIM) * HD;
        for (int tO = tid; tO < WIM * HD; tO += 320) sQ[tO] = src[tO];
    }
#pragma unroll 1
    for (int r = 0; r < WSZ; r++) {
        int ky = qy + r - 7;
        float* dst = sA + r * WIM * HD;
        if ((unsigned)ky < HI) {
            const float* src = g_kp + (size_t)(nh_base + ky * WIM) * HD;
            for (int tO = tid; tO < WIM * HD; tO += 320) dst[tO] = src[tO];
        } else {
            for (int tO = tid; tO < WIM * HD; tO += 320) dst[tO] = 0.0f;
        }
    }
    {
        const float* src = relw_g + (size_t)h * WS2 * HD;
        for (int tO = tid; tO < WS2 * HD; tO += 320) sR[tO] = src[tO];
    }
    __syncthreads();

    // ---- logits: thread = (qx, w-group of 8); q cached in registers ----
    {
        int qx = tid >> 3, g = tid & 7;
        const float4* q4 = reinterpret_cast<const float4*>(sQ + qx * HD);
        float4 qv[8];
#pragma unroll
        for (int u = 0; u < 8; u++) qv[u] = q4[u];
        const float* rb = relb_g + (size_t)h * WS2;
        for (int w = g; w < WS2; w += 8) {
            int wy = w / WSZ, wx = w - wy * WSZ;
            int ky = qy + wy - 7, kx = qx + wx - 7;
            bool img = ((unsigned)ky < HI) & ((unsigned)kx < WIM);
            int kxc = min(max(kx, 0), WIM - 1);
            const float4* k4 = reinterpret_cast<const float4*>(sA + (wy * WIM + kxc) * HD);
            const float4* r4 = reinterpret_cast<const float4*>(sR + w * HD);
            float qk = 0.0f, rl = 0.0f;
#pragma unroll
            for (int u = 0; u < 8; u++) {
                float4 kv = k4[u], rv = r4[u];
                qk = fmaf(qv[u].x, kv.x, qk); qk = fmaf(qv[u].y, kv.y, qk);
                qk = fmaf(qv[u].z, kv.z, qk); qk = fmaf(qv[u].w, kv.w, qk);
                rl = fmaf(qv[u].x, rv.x, rl); rl = fmaf(qv[u].y, rv.y, rl);
                rl = fmaf(qv[u].z, rv.z, rl); rl = fmaf(qv[u].w, rv.w, rl);
            }
            sL[qx * WS2 + w] = (img ? qk : -NEGV) + rl + rb[w];
        }
    }
    __syncthreads();

    // ---- softmax per query (warp handles 4 queries), write attn out ----
    {
        int warp = tid >> 5, lane = tid & 31;
#pragma unroll 1
        for (int qq = 0; qq < 4; qq++) {
            int qx = warp * 4 + qq;
            float* Lp = sL + qx * WS2;
            float vals[8];
            float m = -3.0e38f;
#pragma unroll
            for (int u = 0; u < 8; u++) {
                int w = lane + u * 32;
                vals[u] = (w < WS2) ? Lp[w] : -3.0e38f;
                m = fmaxf(m, vals[u]);
            }
#pragma unroll
            for (int off = 16; off > 0; off >>= 1)
                m = fmaxf(m, __shfl_xor_sync(0xffffffffu, m, off));
            float s = 0.0f;
#pragma unroll
            for (int u = 0; u < 8; u++) { float p = __expf(vals[u] - m); vals[u] = p; s += p; }
#pragma unroll
            for (int off = 16; off > 0; off >>= 1)
                s += __shfl_xor_sync(0xffffffffu, s, off);
            float inv = 1.0f / s;
            float* gp = attn_out ? attn_out + (size_t)(nh_base + qy * WIM + qx) * WS2 : nullptr;
#pragma unroll
            for (int u = 0; u < 8; u++) {
                int w = lane + u * 32;
                if (w < WS2) {
                    float p = vals[u] * inv;
                    Lp[w] = p;
                    if (gp) gp[w] = p;
                }
            }
        }
    }
    __syncthreads();

    // ---- stage V rows (zero-filled OOB) and rel_v, overwriting K/relw ----
#pragma unroll 1
    for (int r = 0; r < WSZ; r++) {
        int ky = qy + r - 7;
        float* dst = sA + r * WIM * HD;
        if ((unsigned)ky < HI) {
            const float* src = g_vp + (size_t)(nh_base + ky * WIM) * HD;
            for (int tO = tid; tO < WIM * HD; tO += 320) dst[tO] = src[tO];
        } else {
            for (int tO = tid; tO < WIM * HD; tO += 320) dst[tO] = 0.0f;
        }
    }
    {
        const float* src = relv_g + (size_t)h * HD * WS2;
        for (int tO = tid; tO < HD * WS2; tO += 320) sR[tO] = src[tO];
    }
    __syncthreads();

    // ---- aggregate: thread = (qx, d). p==0 kills all masked terms. ----
    for (int it = tid; it < WIM * HD; it += 320) {
        int qx = it >> 5, d = it & 31;
        const float* Lp  = sL + qx * WS2;
        const float* rvp = sR + d * WS2;
        float av = 0.0f, ab = 0.0f;
#pragma unroll 1
        for (int wy = 0; wy < WSZ; wy++) {
            const float* vrow = sA + wy * WIM * HD;
            const float* Lrow = Lp + wy * WSZ;
            const float* rrow = rvp + wy * WSZ;
#pragma unroll
            for (int wx = 0; wx < WSZ; wx++) {
                int kx = qx + wx - 7;
                int kxc = min(max(kx, 0), WIM - 1);
                float p = Lrow[wx];
                av = fmaf(p, vrow[kxc * HD + d], av);
                ab = fmaf(p, rrow[wx], ab);
            }
        }
        g_ctx[((size_t)(qy * WIM + qx) * NB + n) * CH + h * HD + d] = av + ab;
    }
}

// ============================================================
// Kernel 3: output projection. out[r][o] = sum_c ctx[r][c]*Wp[o][c] + bp[o]
// r = i*NB + n in [0,3200). grid (o_tiles=4, r_tiles=50), 256 thr.
// ============================================================
__global__ void __launch_bounds__(256) outproj_kernel(
    const float* __restrict__ Wp, const float* __restrict__ bp,
    float* __restrict__ out)
{
    __shared__ __align__(16) float As[64][32];
    __shared__ __align__(16) float BsT[64][33];

    int r0 = blockIdx.y * 64, o0 = blockIdx.x * 64;
    int tid = threadIdx.x;
    int tx = tid & 15, ty = tid >> 4;

    float acc[4][4] = {};

    for (int k0 = 0; k0 < CH; k0 += 32) {
#pragma unroll
        for (int s = 0; s < 8; s++) {
            int idx = tid + s * 256;
            int row = idx >> 5, col = idx & 31;
            As[row][col]  = g_ctx[(size_t)(r0 + row) * CH + k0 + col];
            BsT[row][col] = Wp[(size_t)(o0 + row) * CH + k0 + col];
        }
        __syncthreads();
#pragma unroll
        for (int cc = 0; cc < 32; cc++) {
            float aa[4], bb[4];
#pragma unroll
            for (int i = 0; i < 4; i++) aa[i] = As[ty * 4 + i][cc];
#pragma unroll
            for (int j = 0; j < 4; j++) bb[j] = BsT[tx * 4 + j][cc];
#pragma unroll
            for (int i = 0; i < 4; i++)
#pragma unroll
                for (int j = 0; j < 4; j++)
                    acc[i][j] = fmaf(aa[i], bb[j], acc[i][j]);
        }
        __syncthreads();
    }

#pragma unroll
    for (int i = 0; i < 4; i++) {
        int r = r0 + ty * 4 + i;
#pragma unroll
        for (int j = 0; j < 4; j++) {
            int o = o0 + tx * 4 + j;
            out[(size_t)r * CH + o] = acc[i][j] + bp[o];
        }
    }
}

// ============================================================
extern "C" void kernel_launch(void* const* d_in, const int* in_sizes, int n_in,
                              void* d_out, int out_size)
{
    const float* q    = (const float*)d_in[0];
    const float* k    = (const float*)d_in[1];
    const float* v    = (const float*)d_in[2];
    const float* Wq   = (const float*)d_in[3];
    const float* bq   = (const float*)d_in[4];
    const float* Wk   = (const float*)d_in[5];
    const float* bk   = (const float*)d_in[6];
    const float* Wv   = (const float*)d_in[7];
    const float* bv   = (const float*)d_in[8];
    const float* relw = (const float*)d_in[9];
    const float* relb = (const float*)d_in[10];
    const float* relv = (const float*)d_in[11];
    const float* Wp   = (const float*)d_in[12];
    const float* bp   = (const float*)d_in[13];
    (void)in_sizes; (void)n_in;

    float* out  = (float*)d_out;
    float* attn = (out_size >= OUT_ELEMS + ATTN_ELEMS) ? (out + OUT_ELEMS) : nullptr;

    static bool s_init = false;
    if (!s_init) {
        cudaFuncSetAttribute(attn_kernel,
                             cudaFuncAttributeMaxDynamicSharedMemorySize, SM_BYTES);
        s_init = true;
    }

    proj_kernel<<<dim3(25, 4, 6), 256>>>(q, k, v, Wq, bq, Wk, bk, Wv, bv);
    attn_kernel<<<dim3(HI, NHD, NB), 320, SM_BYTES>>>(relw, relb, relv, attn);
    outproj_kernel<<<dim3(4, 50), 256>>>(Wp, bp, out);
}

// round 4
// speedup vs baseline: 3.4916x; 3.4916x over previous
#include <cuda_runtime.h>
#include <math.h>

#define NB   2
#define NHD  8
#define HD   32
#define CH   256
#define HI   40
#define WIM  40
#define HW   1600
#define WSZ  15
#define WS2  225
#define NEGV 1e8f
#define INV_T 0.17677669529663687f   // 1/sqrt(32)

#define OUT_ELEMS  (HW*NB*CH)            // 819200
#define ATTN_ELEMS (NB*NHD*HW*WS2)       // 5760000

// ---- scratch (no allocations allowed) ----
__device__ float g_qp[NB*NHD*HW*HD];   // [n][h][i][d], unscaled
__device__ float g_kp[NB*NHD*HW*HD];   // [n][h][j][d], scaled by 1/T
__device__ float g_vp[NB*NHD*HW*HD];   // [n][h][j][d]
__device__ float g_ctx[HW*NB*CH];      // [i][n][c] pre-output-projection

// ============================================================
// Kernel 1: fused QKV 1x1-conv projection. (unchanged from R3)
// ============================================================
__global__ void __launch_bounds__(256) proj_kernel(
    const float* __restrict__ q, const float* __restrict__ k, const float* __restrict__ v,
    const float* __restrict__ Wq, const float* __restrict__ bq,
    const float* __restrict__ Wk, const float* __restrict__ bk,
    const float* __restrict__ Wv, const float* __restrict__ bv)
{
    __shared__ __align__(16) float Ws[64][32];
    __shared__ __align__(16) float Bs[32][64];

    int z = blockIdx.z;
    int n = z & 1, t = z >> 1;
    const float* X; const float* W; const float* b; float* Y; float scale;
    if (t == 0)      { X = q; W = Wq; b = bq; Y = g_qp; scale = 1.0f;  }
    else if (t == 1) { X = k; W = Wk; b = bk; Y = g_kp; scale = INV_T; }
    else             { X = v; W = Wv; b = bv; Y = g_vp; scale = 1.0f;  }
    X += (size_t)n * CH * HW;

    int o0 = blockIdx.y * 64, p0 = blockIdx.x * 64;
    int tid = threadIdx.x;
    int tx = tid & 15, ty = tid >> 4;

    float acc[4][4] = {};

    for (int k0 = 0; k0 < CH; k0 += 32) {
#pragma unroll
        for (int s = 0; s < 8; s++) {
            int idx = tid + s * 256;
            int row = idx >> 5, col = idx & 31;
            Ws[row][col] = W[(size_t)(o0 + row) * CH + k0 + col];
        }
#pragma unroll
        for (int s = 0; s < 8; s++) {
            int idx = tid + s * 256;
            int col = idx & 63, row = idx >> 6;
            Bs[row][col] = X[(size_t)(k0 + row) * HW + p0 + col];
        }
        __syncthreads();
#pragma unroll
        for (int cc = 0; cc < 32; cc++) {
            float4 b4 = *reinterpret_cast<const float4*>(&Bs[cc][tx * 4]);
            float bb[4] = {b4.x, b4.y, b4.z, b4.w};
            float aa[4];
#pragma unroll
            for (int i = 0; i < 4; i++) aa[i] = Ws[ty * 4 + i][cc];
#pragma unroll
            for (int i = 0; i < 4; i++)
#pragma unroll
                for (int j = 0; j < 4; j++)
                    acc[i][j] = fmaf(aa[i], bb[j], acc[i][j]);
        }
        __syncthreads();
    }

#pragma unroll
    for (int i = 0; i < 4; i++) {
        int o = o0 + ty * 4 + i;
        int h = o >> 5, d = o & 31;
        float bias = b[o];
#pragma unroll
        for (int j = 0; j < 4; j++) {
            int p = p0 + tx * 4 + j;
            float val = (acc[i][j] + bias) * scale;
            Y[((size_t)(n * NHD + h) * HW + p) * HD + d] = val;
        }
    }
}

// ============================================================
// Kernel 2: local attention v2. Block per (qy, h, n). 320 threads.
// Bank-conflict-free smem layouts:
//   K: pitch-33 per key, x padded +-7  -> lanes over consecutive qx read
//      consecutive banks (scalar LDS).
//   V: natural pitch-32, x padded +-7  -> lanes over d, conflict-free.
//   relw [w][d] (broadcast), relv [d][w] ((d+w)%32 distinct).
// ============================================================
#define PADW  54            // WIM + 14
#define KSTR  33            // odd pitch blocks vectorization & conflicts
#define SM_A      0
#define A_FLOATS  26732     // >= 15*54*33 = 26730, mult of 4
#define SM_L      26732     // 40*225 = 9000
#define SM_R      35732     // 7200 (relw, then relv)   (16B aligned)
#define SM_B      42932     // 240 (relb)
#define SM_FLOATS 43172
#define SM_BYTES  (SM_FLOATS * 4)

__global__ void __launch_bounds__(320, 1) attn_kernel(
    const float* __restrict__ relw_g,   // [NHD][WS2][HD]
    const float* __restrict__ relb_g,   // [NHD][WS2]
    const float* __restrict__ relv_g,   // [NHD][HD][WS2]
    float* __restrict__ attn_out)       // may be null
{
    int qy = blockIdx.x, h = blockIdx.y, n = blockIdx.z;
    int tid = threadIdx.x;
    extern __shared__ __align__(16) float sm[];
    float* sA = sm + SM_A;
    float* sL = sm + SM_L;
    float* sR = sm + SM_R;
    float* sB = sm + SM_B;

    int nh_base = (n * NHD + h) * HW;
    const float4 z4 = make_float4(0.f, 0.f, 0.f, 0.f);

    // ---- zero region A (covers x-pads and OOB rows) ----
    for (int i = tid; i < A_FLOATS / 4; i += 320)
        reinterpret_cast<float4*>(sA)[i] = z4;
    // relw [w][d]: contiguous copy
    {
        const float4* src = reinterpret_cast<const float4*>(relw_g + (size_t)h * WS2 * HD);
        float4* dst = reinterpret_cast<float4*>(sR);
        for (int i = tid; i < WS2 * HD / 4; i += 320) dst[i] = src[i];
    }
    {
        const float* src = relb_g + (size_t)h * WS2;
        for (int i = tid; i < WS2; i += 320) sB[i] = src[i];
    }
    __syncthreads();

    // ---- stage K interior: dst pitch 33 per key ----
#pragma unroll 1
    for (int r = 0; r < WSZ; r++) {
        int ky = qy + r - 7;
        if ((unsigned)ky < HI) {
            const float* src = g_kp + (size_t)(nh_base + ky * WIM) * HD;
            float* dst = sA + (r * PADW + 7) * KSTR;
            for (int i = tid; i < WIM * HD; i += 320) {
                int kx = i >> 5, d = i & 31;
                dst[kx * KSTR + d] = src[i];
            }
        }
    }
    __syncthreads();

    // ---- logits: thread = (qx = tid%40, wg = tid/40). scalar LDS, bank+1/lane ----
    {
        int qx = tid % 40;
        int wg = tid / 40;
        float qv[HD];
        {
            const float4* qsrc = reinterpret_cast<const float4*>(
                g_qp + (size_t)(nh_base + qy * WIM + qx) * HD);
#pragma unroll
            for (int u = 0; u < 8; u++) {
                float4 t4 = qsrc[u];
                qv[4*u] = t4.x; qv[4*u+1] = t4.y; qv[4*u+2] = t4.z; qv[4*u+3] = t4.w;
            }
        }
#pragma unroll 1
        for (int w = wg; w < WS2; w += 8) {
            int wy = w / WSZ, wx = w - wy * WSZ;
            int ky = qy + wy - 7, kx = qx + wx - 7;
            bool img = ((unsigned)ky < HI) & ((unsigned)kx < WIM);
            const float* kp = sA + (wy * PADW + qx + wx) * KSTR;  // (kx+7)=qx+wx
            const float* rp = sR + w * HD;
            float qk = 0.f, rl = 0.f;
#pragma unroll
            for (int d = 0; d < HD; d++) {
                qk = fmaf(qv[d], kp[d], qk);
                rl = fmaf(qv[d], rp[d], rl);
            }
            sL[qx * WS2 + w] = (img ? qk : -NEGV) + rl + sB[w];
        }
    }
    __syncthreads();

    // ---- softmax per query (warp handles 4 queries), write attn out ----
    {
        int warp = tid >> 5, lane = tid & 31;
#pragma unroll 1
        for (int qq = 0; qq < 4; qq++) {
            int qx = warp * 4 + qq;
            float* Lp = sL + qx * WS2;
            float vals[8];
            float m = -3.0e38f;
#pragma unroll
            for (int u = 0; u < 8; u++) {
                int w = lane + u * 32;
                vals[u] = (w < WS2) ? Lp[w] : -3.0e38f;
                m = fmaxf(m, vals[u]);
            }
#pragma unroll
            for (int off = 16; off > 0; off >>= 1)
                m = fmaxf(m, __shfl_xor_sync(0xffffffffu, m, off));
            float s = 0.0f;
#pragma unroll
            for (int u = 0; u < 8; u++) { float p = __expf(vals[u] - m); vals[u] = p; s += p; }
#pragma unroll
            for (int off = 16; off > 0; off >>= 1)
                s += __shfl_xor_sync(0xffffffffu, s, off);
            float inv = 1.0f / s;
            float* gp = attn_out ? attn_out + (size_t)(nh_base + qy * WIM + qx) * WS2 : nullptr;
#pragma unroll
            for (int u = 0; u < 8; u++) {
                int w = lane + u * 32;
                if (w < WS2) {
                    float p = vals[u] * inv;
                    Lp[w] = p;
                    if (gp) gp[w] = p;
                }
            }
        }
    }
    __syncthreads();

    // ---- stage V (natural pitch 32, x padded) + relv [d][w] ----
    for (int i = tid; i < A_FLOATS / 4; i += 320)
        reinterpret_cast<float4*>(sA)[i] = z4;
    __syncthreads();
#pragma unroll 1
    for (int r = 0; r < WSZ; r++) {
        int ky = qy + r - 7;
        if ((unsigned)ky < HI) {
            const float4* src = reinterpret_cast<const float4*>(
                g_vp + (size_t)(nh_base + ky * WIM) * HD);
            float4* dst = reinterpret_cast<float4*>(sA + (r * PADW + 7) * HD);
            for (int i = tid; i < WIM * HD / 4; i += 320) dst[i] = src[i];
        }
    }
    {
        const float4* src = reinterpret_cast<const float4*>(relv_g + (size_t)h * HD * WS2);
        float4* dst = reinterpret_cast<float4*>(sR);
        for (int i = tid; i < HD * WS2 / 4; i += 320) dst[i] = src[i];
    }
    __syncthreads();

    // ---- aggregation: warp = 4 consecutive queries, lane = d ----
    {
        int warp = tid >> 5, lane = tid & 31;
        int q0 = warp * 4;
        float av[4] = {0.f, 0.f, 0.f, 0.f};
        float ab[4] = {0.f, 0.f, 0.f, 0.f};
#pragma unroll 1
        for (int c = 0; c < 7; c++) {           // 7 full chunks of 32 w
            int wbase = c * 32;
            float pv[4];
#pragma unroll
            for (int j = 0; j < 4; j++)
                pv[j] = sL[(q0 + j) * WS2 + wbase + lane];
#pragma unroll 4
            for (int u = 0; u < 32; u++) {
                int w = wbase + u;
                int wy = w / WSZ, wx = w - wy * WSZ;
                float rl = sR[lane * WS2 + w];
                const float* vb = sA + (wy * PADW + wx + q0) * HD + lane;
#pragma unroll
                for (int j = 0; j < 4; j++) {
                    float p = __shfl_sync(0xffffffffu, pv[j], u);
                    av[j] = fmaf(p, vb[j * HD], av[j]);
                    ab[j] = fmaf(p, rl, ab[j]);
                }
            }
        }
        {   // tail: w = 224 (wy=14, wx=14)
            float rl = sR[lane * WS2 + 224];
            const float* vb = sA + (14 * PADW + 14 + q0) * HD + lane;
#pragma unroll
            for (int j = 0; j < 4; j++) {
                float p = sL[(q0 + j) * WS2 + 224];
                av[j] = fmaf(p, vb[j * HD], av[j]);
                ab[j] = fmaf(p, rl, ab[j]);
            }
        }
#pragma unroll
        for (int j = 0; j < 4; j++) {
            int qx = q0 + j;
            g_ctx[(size_t)((qy * WIM + qx) * NB + n) * CH + h * HD + lane] = av[j] + ab[j];
        }
    }
}

// ============================================================
// Kernel 3: output projection. (unchanged from R3)
// ============================================================
__global__ void __launch_bounds__(256) outproj_kernel(
    const float* __restrict__ Wp, const float* __restrict__ bp,
    float* __restrict__ out)
{
    __shared__ __align__(16) float As[64][32];
    __shared__ __align__(16) float BsT[64][33];

    int r0 = blockIdx.y * 64, o0 = blockIdx.x * 64;
    int tid = threadIdx.x;
    int tx = tid & 15, ty = tid >> 4;

    float acc[4][4] = {};

    for (int k0 = 0; k0 < CH; k0 += 32) {
#pragma unroll
        for (int s = 0; s < 8; s++) {
            int idx = tid + s * 256;
            int row = idx >> 5, col = idx & 31;
            As[row][col]  = g_ctx[(size_t)(r0 + row) * CH + k0 + col];
            BsT[row][col] = Wp[(size_t)(o0 + row) * CH + k0 + col];
        }
        __syncthreads();
#pragma unroll
        for (int cc = 0; cc < 32; cc++) {
            float aa[4], bb[4];
#pragma unroll
            for (int i = 0; i < 4; i++) aa[i] = As[ty * 4 + i][cc];
#pragma unroll
            for (int j = 0; j < 4; j++) bb[j] = BsT[tx * 4 + j][cc];
#pragma unroll
            for (int i = 0; i < 4; i++)
#pragma unroll
                for (int j = 0; j < 4; j++)
                    acc[i][j] = fmaf(aa[i], bb[j], acc[i][j]);
        }
        __syncthreads();
    }

#pragma unroll
    for (int i = 0; i < 4; i++) {
        int r = r0 + ty * 4 + i;
#pragma unroll
        for (int j = 0; j < 4; j++) {
            int o = o0 + tx * 4 + j;
            out[(size_t)r * CH + o] = acc[i][j] + bp[o];
        }
    }
}

// ============================================================
extern "C" void kernel_launch(void* const* d_in, const int* in_sizes, int n_in,
                              void* d_out, int out_size)
{
    const float* q    = (const float*)d_in[0];
    const float* k    = (const float*)d_in[1];
    const float* v    = (const float*)d_in[2];
    const float* Wq   = (const float*)d_in[3];
    const float* bq   = (const float*)d_in[4];
    const float* Wk   = (const float*)d_in[5];
    const float* bk   = (const float*)d_in[6];
    const float* Wv   = (const float*)d_in[7];
    const float* bv   = (const float*)d_in[8];
    const float* relw = (const float*)d_in[9];
    const float* relb = (const float*)d_in[10];
    const float* relv = (const float*)d_in[11];
    const float* Wp   = (const float*)d_in[12];
    const float* bp   = (const float*)d_in[13];
    (void)in_sizes; (void)n_in;

    float* out  = (float*)d_out;
    float* attn = (out_size >= OUT_ELEMS + ATTN_ELEMS) ? (out + OUT_ELEMS) : nullptr;

    static bool s_init = false;
    if (!s_init) {
        cudaFuncSetAttribute(attn_kernel,
                             cudaFuncAttributeMaxDynamicSharedMemorySize, SM_BYTES);
        s_init = true;
    }

    proj_kernel<<<dim3(25, 4, 6), 256>>>(q, k, v, Wq, bq, Wk, bk, Wv, bv);
    attn_kernel<<<dim3(HI, NHD, NB), 320, SM_BYTES>>>(relw, relb, relv, attn);
    outproj_kernel<<<dim3(4, 50), 256>>>(Wp, bp, out);
}

// round 5
// speedup vs baseline: 4.4216x; 1.2664x over previous
#include <cuda_runtime.h>
#include <math.h>

#define NB   2
#define NHD  8
#define HD   32
#define CH   256
#define HI   40
#define WIM  40
#define HW   1600
#define WSZ  15
#define WS2  225
#define NEGV 1e8f
#define INV_T 0.17677669529663687f   // 1/sqrt(32)

#define OUT_ELEMS  (HW*NB*CH)            // 819200
#define ATTN_ELEMS (NB*NHD*HW*WS2)       // 5760000

// ---- scratch ----
__device__ float g_qp[NB*NHD*HW*HD];
__device__ float g_kp[NB*NHD*HW*HD];   // scaled by 1/T
__device__ float g_vp[NB*NHD*HW*HD];
__device__ float g_ctx[HW*NB*CH];

// ============================================================
// Kernel 1: fused QKV projection, 128x64 block tile, 8x4 per thread.
// grid: (p_tiles=25, o_tiles=2, z=6: n = z&1, tensor = z>>1), 256 thr
// ============================================================
__global__ void __launch_bounds__(256) proj_kernel(
    const float* __restrict__ q, const float* __restrict__ k, const float* __restrict__ v,
    const float* __restrict__ Wq, const float* __restrict__ bq,
    const float* __restrict__ Wk, const float* __restrict__ bk,
    const float* __restrict__ Wv, const float* __restrict__ bv)
{
    __shared__ __align__(16) float Ws[128 * 33];
    __shared__ __align__(16) float Bs[32][64];

    int z = blockIdx.z;
    int n = z & 1, t = z >> 1;
    const float* X; const float* W; const float* b; float* Y; float scale;
    if (t == 0)      { X = q; W = Wq; b = bq; Y = g_qp; scale = 1.0f;  }
    else if (t == 1) { X = k; W = Wk; b = bk; Y = g_kp; scale = INV_T; }
    else             { X = v; W = Wv; b = bv; Y = g_vp; scale = 1.0f;  }
    X += (size_t)n * CH * HW;

    int o0 = blockIdx.y * 128, p0 = blockIdx.x * 64;
    int tid = threadIdx.x;
    int tx = tid & 15, ty = tid >> 4;

    float acc[8][4] = {};

    for (int k0 = 0; k0 < CH; k0 += 32) {
#pragma unroll
        for (int s = 0; s < 16; s++) {
            int idx = tid + s * 256;
            int row = idx >> 5, col = idx & 31;
            Ws[row * 33 + col] = W[(size_t)(o0 + row) * CH + k0 + col];
        }
#pragma unroll
        for (int s = 0; s < 8; s++) {
            int idx = tid + s * 256;
            int col = idx & 63, row = idx >> 6;
            Bs[row][col] = X[(size_t)(k0 + row) * HW + p0 + col];
        }
        __syncthreads();
#pragma unroll
        for (int cc = 0; cc < 32; cc++) {
            float4 b4 = *reinterpret_cast<const float4*>(&Bs[cc][tx * 4]);
            float bb[4] = {b4.x, b4.y, b4.z, b4.w};
            float aa[8];
#pragma unroll
            for (int i = 0; i < 8; i++) aa[i] = Ws[(ty * 8 + i) * 33 + cc];
#pragma unroll
            for (int i = 0; i < 8; i++)
#pragma unroll
                for (int j = 0; j < 4; j++)
                    acc[i][j] = fmaf(aa[i], bb[j], acc[i][j]);
        }
        __syncthreads();
    }

#pragma unroll
    for (int i = 0; i < 8; i++) {
        int o = o0 + ty * 8 + i;
        int h = o >> 5, d = o & 31;
        float bias = b[o];
#pragma unroll
        for (int j = 0; j < 4; j++) {
            int p = p0 + tx * 4 + j;
            float val = (acc[i][j] + bias) * scale;
            Y[((size_t)(n * NHD + h) * HW + p) * HD + d] = val;
        }
    }
}

// ============================================================
// Kernel 2: local attention v3. Block per (qy, h, n). 320 threads.
//   K: pitch-36 per key (float4 conflict-free: lane stride = 4 banks),
//      x padded +-7.
//   V: pitch-32, x padded +-7 (lane = d, conflict-free).
//   relw [w][d] pitch 36 (float4), relv [d][w] pitch 228 (float4, 4-bank
//      lane stride).
// ============================================================
#define PADW  54
#define KP    36
#define SM_A      0          // 15*54*36 = 29160 floats
#define SM_L      29160      // 40*225  = 9000
#define SM_R      38160      // max(225*36=8100, 32*228=7296)
#define SM_B      46260      // 225 (+pad)
#define SM_FLOATS 46500
#define SM_BYTES  (SM_FLOATS * 4)

__global__ void __launch_bounds__(320, 1) attn_kernel(
    const float* __restrict__ relw_g,   // [NHD][WS2][HD]
    const float* __restrict__ relb_g,   // [NHD][WS2]
    const float* __restrict__ relv_g,   // [NHD][HD][WS2]
    float* __restrict__ attn_out)       // may be null
{
    int qy = blockIdx.x, h = blockIdx.y, n = blockIdx.z;
    int tid = threadIdx.x;
    extern __shared__ __align__(16) float sm[];
    float* sA = sm + SM_A;
    float* sL = sm + SM_L;
    float* sR = sm + SM_R;
    float* sB = sm + SM_B;

    int nh_base = (n * NHD + h) * HW;
    const float4 z4 = make_float4(0.f, 0.f, 0.f, 0.f);

    // ---- zero K region (covers x-pads and OOB rows) ----
    for (int i = tid; i < (WSZ * PADW * KP) / 4; i += 320)
        reinterpret_cast<float4*>(sA)[i] = z4;
    // relw [w][d] -> pitch 36
    {
        const float* src = relw_g + (size_t)h * WS2 * HD;
        for (int i = tid; i < WS2 * HD; i += 320) {
            int w = i >> 5, d = i & 31;
            sR[w * KP + d] = src[i];
        }
    }
    {
        const float* src = relb_g + (size_t)h * WS2;
        for (int i = tid; i < WS2; i += 320) sB[i] = src[i];
    }
    __syncthreads();

    // ---- stage K interior (one float4 per thread per row) ----
    {
        int kx = tid >> 3, u = tid & 7;
#pragma unroll 1
        for (int r = 0; r < WSZ; r++) {
            int ky = qy + r - 7;
            if ((unsigned)ky < HI) {
                const float4* src = reinterpret_cast<const float4*>(
                    g_kp + (size_t)(nh_base + ky * WIM) * HD);
                float* dst = sA + (r * PADW + 7 + kx) * KP + 4 * u;
                *reinterpret_cast<float4*>(dst) = src[tid];
            }
        }
    }
    __syncthreads();

    // ---- logits: thread = (qx = tid%40, wg = tid/40), float4 LDS ----
    {
        int qx = tid % 40;
        int wg = tid / 40;
        float4 qv[8];
        {
            const float4* qsrc = reinterpret_cast<const float4*>(
                g_qp + (size_t)(nh_base + qy * WIM + qx) * HD);
#pragma unroll
            for (int u = 0; u < 8; u++) qv[u] = qsrc[u];
        }
#pragma unroll 1
        for (int w = wg; w < WS2; w += 8) {
            int wy = w / WSZ, wx = w - wy * WSZ;
            int ky = qy + wy - 7, kx = qx + wx - 7;
            bool img = ((unsigned)ky < HI) & ((unsigned)kx < WIM);
            const float4* k4 = reinterpret_cast<const float4*>(
                sA + (wy * PADW + qx + wx) * KP);
            const float4* r4 = reinterpret_cast<const float4*>(sR + w * KP);
            float4 aqk = z4, arl = z4;
#pragma unroll
            for (int u = 0; u < 8; u++) {
                float4 kv = k4[u], rv = r4[u], qq = qv[u];
                aqk.x = fmaf(qq.x, kv.x, aqk.x);
                aqk.y = fmaf(qq.y, kv.y, aqk.y);
                aqk.z = fmaf(qq.z, kv.z, aqk.z);
                aqk.w = fmaf(qq.w, kv.w, aqk.w);
                arl.x = fmaf(qq.x, rv.x, arl.x);
                arl.y = fmaf(qq.y, rv.y, arl.y);
                arl.z = fmaf(qq.z, rv.z, arl.z);
                arl.w = fmaf(qq.w, rv.w, arl.w);
            }
            float qk = (aqk.x + aqk.y) + (aqk.z + aqk.w);
            float rl = (arl.x + arl.y) + (arl.z + arl.w);
            sL[qx * WS2 + w] = (img ? qk : -NEGV) + rl + sB[w];
        }
    }
    __syncthreads();

    // ---- softmax per query (warp handles 4 queries) ----
    {
        int warp = tid >> 5, lane = tid & 31;
#pragma unroll 1
        for (int qq = 0; qq < 4; qq++) {
            int qx = warp * 4 + qq;
            float* Lp = sL + qx * WS2;
            float vals[8];
            float m = -3.0e38f;
#pragma unroll
            for (int u = 0; u < 8; u++) {
                int w = lane + u * 32;
                vals[u] = (w < WS2) ? Lp[w] : -3.0e38f;
                m = fmaxf(m, vals[u]);
            }
#pragma unroll
            for (int off = 16; off > 0; off >>= 1)
                m = fmaxf(m, __shfl_xor_sync(0xffffffffu, m, off));
            float s = 0.0f;
#pragma unroll
            for (int u = 0; u < 8; u++) { float p = __expf(vals[u] - m); vals[u] = p; s += p; }
#pragma unroll
            for (int off = 16; off > 0; off >>= 1)
                s += __shfl_xor_sync(0xffffffffu, s, off);
            float inv = 1.0f / s;
            float* gp = attn_out ? attn_out + (size_t)(nh_base + qy * WIM + qx) * WS2 : nullptr;
#pragma unroll
            for (int u = 0; u < 8; u++) {
                int w = lane + u * 32;
                if (w < WS2) {
                    float p = vals[u] * inv;
                    Lp[w] = p;
                    if (gp) gp[w] = p;
                }
            }
        }
    }
    __syncthreads();

    // ---- zero V region, then stage V (pitch 32) + relv (pitch 228) ----
    for (int i = tid; i < (WSZ * PADW * HD) / 4; i += 320)
        reinterpret_cast<float4*>(sA)[i] = z4;
    __syncthreads();
    {
        int kx = tid >> 3, u = tid & 7;
#pragma unroll 1
        for (int r = 0; r < WSZ; r++) {
            int ky = qy + r - 7;
            if ((unsigned)ky < HI) {
                const float4* src = reinterpret_cast<const float4*>(
                    g_vp + (size_t)(nh_base + ky * WIM) * HD);
                float* dst = sA + (r * PADW + 7 + kx) * HD + 4 * u;
                *reinterpret_cast<float4*>(dst) = src[tid];
            }
        }
    }
    {
        const float* src = relv_g + (size_t)h * HD * WS2;
        for (int i = tid; i < HD * WS2; i += 320) {
            int d = i / WS2, w = i - d * WS2;
            sR[d * 228 + w] = src[i];
        }
    }
    __syncthreads();

    // ---- aggregation: warp = 4 consecutive queries, lane = d ----
    {
        int warp = tid >> 5, lane = tid & 31;
        int q0 = warp * 4;
        float av[4] = {0.f, 0.f, 0.f, 0.f};
        float ab[4] = {0.f, 0.f, 0.f, 0.f};
#pragma unroll
        for (int c = 0; c < 7; c++) {           // fully unrolled: wy/wx/u immediates
            int wbase = c * 32;
            float pv[4];
#pragma unroll
            for (int j = 0; j < 4; j++)
                pv[j] = sL[(q0 + j) * WS2 + wbase + lane];
#pragma unroll
            for (int ug = 0; ug < 8; ug++) {
                float4 rlq = *reinterpret_cast<const float4*>(
                    sR + lane * 228 + wbase + ug * 4);
                float rls[4] = {rlq.x, rlq.y, rlq.z, rlq.w};
#pragma unroll
                for (int uu = 0; uu < 4; uu++) {
                    int u = ug * 4 + uu;
                    int w = wbase + u;
                    int wy = w / WSZ, wx = w - wy * WSZ;
                    const float* vb = sA + (wy * PADW + wx + q0) * HD + lane;
                    float rl = rls[uu];
#pragma unroll
                    for (int j = 0; j < 4; j++) {
                        float p = __shfl_sync(0xffffffffu, pv[j], u);
                        av[j] = fmaf(p, vb[j * HD], av[j]);
                        ab[j] = fmaf(p, rl, ab[j]);
                    }
                }
            }
        }
        {   // tail: w = 224 (wy=14, wx=14)
            float rl = sR[lane * 228 + 224];
            const float* vb = sA + (14 * PADW + 14 + q0) * HD + lane;
#pragma unroll
            for (int j = 0; j < 4; j++) {
                float p = sL[(q0 + j) * WS2 + 224];
                av[j] = fmaf(p, vb[j * HD], av[j]);
                ab[j] = fmaf(p, rl, ab[j]);
            }
        }
#pragma unroll
        for (int j = 0; j < 4; j++) {
            int qx = q0 + j;
            g_ctx[(size_t)((qy * WIM + qx) * NB + n) * CH + h * HD + lane] = av[j] + ab[j];
        }
    }
}

// ============================================================
// Kernel 3: output projection (unchanged).
// ============================================================
__global__ void __launch_bounds__(256) outproj_kernel(
    const float* __restrict__ Wp, const float* __restrict__ bp,
    float* __restrict__ out)
{
    __shared__ __align__(16) float As[64][32];
    __shared__ __align__(16) float BsT[64][33];

    int r0 = blockIdx.y * 64, o0 = blockIdx.x * 64;
    int tid = threadIdx.x;
    int tx = tid & 15, ty = tid >> 4;

    float acc[4][4] = {};

    for (int k0 = 0; k0 < CH; k0 += 32) {
#pragma unroll
        for (int s = 0; s < 8; s++) {
            int idx = tid + s * 256;
            int row = idx >> 5, col = idx & 31;
            As[row][col]  = g_ctx[(size_t)(r0 + row) * CH + k0 + col];
            BsT[row][col] = Wp[(size_t)(o0 + row) * CH + k0 + col];
        }
        __syncthreads();
#pragma unroll
        for (int cc = 0; cc < 32; cc++) {
            float aa[4], bb[4];
#pragma unroll
            for (int i = 0; i < 4; i++) aa[i] = As[ty * 4 + i][cc];
#pragma unroll
            for (int j = 0; j < 4; j++) bb[j] = BsT[tx * 4 + j][cc];
#pragma unroll
            for (int i = 0; i < 4; i++)
#pragma unroll
                for (int j = 0; j < 4; j++)
                    acc[i][j] = fmaf(aa[i], bb[j], acc[i][j]);
        }
        __syncthreads();
    }

#pragma unroll
    for (int i = 0; i < 4; i++) {
        int r = r0 + ty * 4 + i;
#pragma unroll
        for (int j = 0; j < 4; j++) {
            int o = o0 + tx * 4 + j;
            out[(size_t)r * CH + o] = acc[i][j] + bp[o];
        }
    }
}

// ============================================================
extern "C" void kernel_launch(void* const* d_in, const int* in_sizes, int n_in,
                              void* d_out, int out_size)
{
    const float* q    = (const float*)d_in[0];
    const float* k    = (const float*)d_in[1];
    const float* v    = (const float*)d_in[2];
    const float* Wq   = (const float*)d_in[3];
    const float* bq   = (const float*)d_in[4];
    const float* Wk   = (const float*)d_in[5];
    const float* bk   = (const float*)d_in[6];
    const float* Wv   = (const float*)d_in[7];
    const float* bv   = (const float*)d_in[8];
    const float* relw = (const float*)d_in[9];
    const float* relb = (const float*)d_in[10];
    const float* relv = (const float*)d_in[11];
    const float* Wp   = (const float*)d_in[12];
    const float* bp   = (const float*)d_in[13];
    (void)in_sizes; (void)n_in;

    float* out  = (float*)d_out;
    float* attn = (out_size >= OUT_ELEMS + ATTN_ELEMS) ? (out + OUT_ELEMS) : nullptr;

    static bool s_init = false;
    if (!s_init) {
        cudaFuncSetAttribute(attn_kernel,
                             cudaFuncAttributeMaxDynamicSharedMemorySize, SM_BYTES);
        s_init = true;
    }

    proj_kernel<<<dim3(25, 2, 6), 256>>>(q, k, v, Wq, bq, Wk, bk, Wv, bv);
    attn_kernel<<<dim3(HI, NHD, NB), 320, SM_BYTES>>>(relw, relb, relv, attn);
    outproj_kernel<<<dim3(4, 50), 256>>>(Wp, bp, out);
}

// round 7
// speedup vs baseline: 4.6861x; 1.0598x over previous
#include <cuda_runtime.h>
#include <math.h>

#define NB   2
#define NHD  8
#define HD   32
#define CH   256
#define HI   40
#define WIM  40
#define HW   1600
#define WSZ  15
#define WS2  225
#define NEGV 1e8f
#define INV_T 0.17677669529663687f   // 1/sqrt(32)

#define OUT_ELEMS  (HW*NB*CH)            // 819200
#define ATTN_ELEMS (NB*NHD*HW*WS2)       // 5760000

// ---- scratch ----
__device__ float g_qp[NB*NHD*HW*HD];
__device__ float g_kp[NB*NHD*HW*HD];   // scaled by 1/T
__device__ float g_vp[NB*NHD*HW*HD];
__device__ float g_ctx[HW*NB*CH];

// ============================================================
// Kernel 1: fused QKV projection, 128x64 tile, 8x4 per thread, occ 2.
// ============================================================
__global__ void __launch_bounds__(256, 2) proj_kernel(
    const float* __restrict__ q, const float* __restrict__ k, const float* __restrict__ v,
    const float* __restrict__ Wq, const float* __restrict__ bq,
    const float* __restrict__ Wk, const float* __restrict__ bk,
    const float* __restrict__ Wv, const float* __restrict__ bv)
{
    __shared__ __align__(16) float Ws[128 * 33];
    __shared__ __align__(16) float Bs[32][64];

    int z = blockIdx.z;
    int n = z & 1, t = z >> 1;
    const float* X; const float* W; const float* b; float* Y; float scale;
    if (t == 0)      { X = q; W = Wq; b = bq; Y = g_qp; scale = 1.0f;  }
    else if (t == 1) { X = k; W = Wk; b = bk; Y = g_kp; scale = INV_T; }
    else             { X = v; W = Wv; b = bv; Y = g_vp; scale = 1.0f;  }
    X += (size_t)n * CH * HW;

    int o0 = blockIdx.y * 128, p0 = blockIdx.x * 64;
    int tid = threadIdx.x;
    int tx = tid & 15, ty = tid >> 4;

    float acc[8][4] = {};

    for (int k0 = 0; k0 < CH; k0 += 32) {
#pragma unroll
        for (int s = 0; s < 16; s++) {
            int idx = tid + s * 256;
            int row = idx >> 5, col = idx & 31;
            Ws[row * 33 + col] = W[(size_t)(o0 + row) * CH + k0 + col];
        }
#pragma unroll
        for (int s = 0; s < 8; s++) {
            int idx = tid + s * 256;
            int col = idx & 63, row = idx >> 6;
            Bs[row][col] = X[(size_t)(k0 + row) * HW + p0 + col];
        }
        __syncthreads();
#pragma unroll
        for (int cc = 0; cc < 32; cc++) {
            float4 b4 = *reinterpret_cast<const float4*>(&Bs[cc][tx * 4]);
            float bb[4] = {b4.x, b4.y, b4.z, b4.w};
            float aa[8];
#pragma unroll
            for (int i = 0; i < 8; i++) aa[i] = Ws[(ty * 8 + i) * 33 + cc];
#pragma unroll
            for (int i = 0; i < 8; i++)
#pragma unroll
                for (int j = 0; j < 4; j++)
                    acc[i][j] = fmaf(aa[i], bb[j], acc[i][j]);
        }
        __syncthreads();
    }

#pragma unroll
    for (int i = 0; i < 8; i++) {
        int o = o0 + ty * 8 + i;
        int h = o >> 5, d = o & 31;
        float bias = b[o];
#pragma unroll
        for (int j = 0; j < 4; j++) {
            int p = p0 + tx * 4 + j;
            float val = (acc[i][j] + bias) * scale;
            Y[((size_t)(n * NHD + h) * HW + p) * HD + d] = val;
        }
    }
}

// ============================================================
// Kernel 2: local attention v4b. Block per (qy, h, n). 640 threads.
//   Interior columns occupy PADW slots 7..46; pads are 0..6 and 47..53.
// ============================================================
#define PADW  54
#define KP    36
#define SM_A      0          // 15*54*36 = 29160 floats
#define SM_L      29160      // 40*225  = 9000
#define SM_R      38160      // relw 225*36=8100 / relv 32*228=7296
#define SM_B      46260      // 225 (+pad)
#define SM_FLOATS 46500
#define SM_BYTES  (SM_FLOATS * 4)

__global__ void __launch_bounds__(640, 1) attn_kernel(
    const float* __restrict__ relw_g,   // [NHD][WS2][HD]
    const float* __restrict__ relb_g,   // [NHD][WS2]
    const float* __restrict__ relv_g,   // [NHD][HD][WS2]
    float* __restrict__ attn_out)       // may be null
{
    int qy = blockIdx.x, h = blockIdx.y, n = blockIdx.z;
    int tid = threadIdx.x;
    extern __shared__ __align__(16) float sm[];
    float* sA = sm + SM_A;
    float* sL = sm + SM_L;
    float* sR = sm + SM_R;
    float* sB = sm + SM_B;

    int nh_base = (n * NHD + h) * HW;
    int qy7 = qy - 7;
    const float4 z4 = make_float4(0.f, 0.f, 0.f, 0.f);

    // ---- stage K (interior + OOB-row zeros merged), pad cols, relw, relb ----
    for (int i = tid; i < WSZ * 320; i += 640) {      // interior / OOB rows
        int r = i / 320, rem = i - r * 320;
        int ky = qy7 + r;
        float4 val = z4;
        if ((unsigned)ky < HI)
            val = reinterpret_cast<const float4*>(
                      g_kp + (size_t)(nh_base + ky * WIM) * HD)[rem];
        int kx = rem >> 3, u = rem & 7;
        *reinterpret_cast<float4*>(sA + (r * PADW + 7 + kx) * KP + 4 * u) = val;
    }
    for (int i = tid; i < WSZ * 112; i += 640) {      // 14 pad cols per row
        int r = i / 112, rem = i - r * 112;
        int c = rem >> 3, u = rem & 7;
        int col = (c < 7) ? c : (c + 40);             // pads: 0..6 and 47..53
        *reinterpret_cast<float4*>(sA + (r * PADW + col) * KP + 4 * u) = z4;
    }
    {   // relw [w][d] -> pitch 36
        const float* src = relw_g + (size_t)h * WS2 * HD;
        for (int i = tid; i < WS2 * HD; i += 640) {
            int w = i >> 5, d = i & 31;
            sR[w * KP + d] = src[i];
        }
    }
    {
        const float* src = relb_g + (size_t)h * WS2;
        for (int i = tid; i < WS2; i += 640) sB[i] = src[i];
    }
    __syncthreads();

    // ---- logits: thread = (qx = tid%40, wg = tid/40 in 0..15) ----
    {
        int qx = tid % 40;
        int wg = tid / 40;
        float4 qv[8];
        {
            const float4* qsrc = reinterpret_cast<const float4*>(
                g_qp + (size_t)(nh_base + qy * WIM + qx) * HD);
#pragma unroll
            for (int u = 0; u < 8; u++) qv[u] = qsrc[u];
        }
#pragma unroll 1
        for (int w = wg; w < WS2; w += 16) {
            int wy = w / WSZ, wx = w - wy * WSZ;
            int ky = qy7 + wy, kx = qx + wx - 7;
            bool img = ((unsigned)ky < HI) & ((unsigned)kx < WIM);
            const float4* k4 = reinterpret_cast<const float4*>(
                sA + (wy * PADW + qx + wx) * KP);
            const float4* r4 = reinterpret_cast<const float4*>(sR + w * KP);
            float4 aqk = z4, arl = z4;
#pragma unroll
            for (int u = 0; u < 8; u++) {
                float4 kv = k4[u], rv = r4[u], qq = qv[u];
                aqk.x = fmaf(qq.x, kv.x, aqk.x);
                aqk.y = fmaf(qq.y, kv.y, aqk.y);
                aqk.z = fmaf(qq.z, kv.z, aqk.z);
                aqk.w = fmaf(qq.w, kv.w, aqk.w);
                arl.x = fmaf(qq.x, rv.x, arl.x);
                arl.y = fmaf(qq.y, rv.y, arl.y);
                arl.z = fmaf(qq.z, rv.z, arl.z);
                arl.w = fmaf(qq.w, rv.w, arl.w);
            }
            float qk = (aqk.x + aqk.y) + (aqk.z + aqk.w);
            float rl = (arl.x + arl.y) + (arl.z + arl.w);
            sL[qx * WS2 + w] = (img ? qk : -NEGV) + rl + sB[w];
        }
    }
    __syncthreads();

    // ---- V + relv staging (writes sA/sR, disjoint from softmax's sL) ----
    for (int i = tid; i < WSZ * 320; i += 640) {
        int r = i / 320, rem = i - r * 320;
        int ky = qy7 + r;
        float4 val = z4;
        if ((unsigned)ky < HI)
            val = reinterpret_cast<const float4*>(
                      g_vp + (size_t)(nh_base + ky * WIM) * HD)[rem];
        reinterpret_cast<float4*>(sA + (r * PADW + 7) * HD)[rem] = val;
    }
    for (int i = tid; i < WSZ * 112; i += 640) {      // V pad cols (pitch 32)
        int r = i / 112, rem = i - r * 112;
        int c = rem >> 3, u = rem & 7;
        int col = (c < 7) ? c : (c + 40);             // pads: 0..6 and 47..53
        *reinterpret_cast<float4*>(sA + (r * PADW + col) * HD + 4 * u) = z4;
    }
    {   // relv [d][w] -> pitch 228
        const float* src = relv_g + (size_t)h * HD * WS2;
        for (int i = tid; i < HD * WS2; i += 640) {
            int d = i / WS2, w = i - d * WS2;
            sR[d * 228 + w] = src[i];
        }
    }

    // ---- softmax: 20 warps x 2 queries (reads/writes sL only) ----
    {
        int warp = tid >> 5, lane = tid & 31;
#pragma unroll 1
        for (int qq = 0; qq < 2; qq++) {
            int qx = warp * 2 + qq;
            float* Lp = sL + qx * WS2;
            float vals[8];
            float m = -3.0e38f;
#pragma unroll
            for (int u = 0; u < 8; u++) {
                int w = lane + u * 32;
                vals[u] = (w < WS2) ? Lp[w] : -3.0e38f;
                m = fmaxf(m, vals[u]);
            }
#pragma unroll
            for (int off = 16; off > 0; off >>= 1)
                m = fmaxf(m, __shfl_xor_sync(0xffffffffu, m, off));
            float s = 0.0f;
#pragma unroll
            for (int u = 0; u < 8; u++) { float p = __expf(vals[u] - m); vals[u] = p; s += p; }
#pragma unroll
            for (int off = 16; off > 0; off >>= 1)
                s += __shfl_xor_sync(0xffffffffu, s, off);
            float inv = 1.0f / s;
            float* gp = attn_out ? attn_out + (size_t)(nh_base + qy * WIM + qx) * WS2 : nullptr;
#pragma unroll
            for (int u = 0; u < 8; u++) {
                int w = lane + u * 32;
                if (w < WS2) {
                    float p = vals[u] * inv;
                    Lp[w] = p;
                    if (gp) gp[w] = p;
                }
            }
        }
    }
    __syncthreads();

    // ---- aggregation: warp = 2 consecutive queries, lane = d ----
    {
        int warp = tid >> 5, lane = tid & 31;
        int q0 = warp * 2;
        float av[2] = {0.f, 0.f};
        float ab[2] = {0.f, 0.f};
#pragma unroll
        for (int c = 0; c < 7; c++) {
            int wbase = c * 32;
            float pv[2];
#pragma unroll
            for (int j = 0; j < 2; j++)
                pv[j] = sL[(q0 + j) * WS2 + wbase + lane];
#pragma unroll
            for (int ug = 0; ug < 8; ug++) {
                float4 rlq = *reinterpret_cast<const float4*>(
                    sR + lane * 228 + wbase + ug * 4);
                float rls[4] = {rlq.x, rlq.y, rlq.z, rlq.w};
#pragma unroll
                for (int uu = 0; uu < 4; uu++) {
                    int u = ug * 4 + uu;
                    int w = wbase + u;
                    int wy = w / WSZ, wx = w - wy * WSZ;
                    const float* vb = sA + (wy * PADW + wx + q0) * HD + lane;
                    float rl = rls[uu];
#pragma unroll
                    for (int j = 0; j < 2; j++) {
                        float p = __shfl_sync(0xffffffffu, pv[j], u);
                        av[j] = fmaf(p, vb[j * HD], av[j]);
                        ab[j] = fmaf(p, rl, ab[j]);
                    }
                }
            }
        }
        {   // tail w = 224 (wy=14, wx=14)
            float rl = sR[lane * 228 + 224];
            const float* vb = sA + (14 * PADW + 14 + q0) * HD + lane;
#pragma unroll
            for (int j = 0; j < 2; j++) {
                float p = sL[(q0 + j) * WS2 + 224];
                av[j] = fmaf(p, vb[j * HD], av[j]);
                ab[j] = fmaf(p, rl, ab[j]);
            }
        }
#pragma unroll
        for (int j = 0; j < 2; j++) {
            int qx = q0 + j;
            g_ctx[(size_t)((qy * WIM + qx) * NB + n) * CH + h * HD + lane] = av[j] + ab[j];
        }
    }
}

// ============================================================
// Kernel 3: output projection (unchanged).
// ============================================================
__global__ void __launch_bounds__(256) outproj_kernel(
    const float* __restrict__ Wp, const float* __restrict__ bp,
    float* __restrict__ out)
{
    __shared__ __align__(16) float As[64][32];
    __shared__ __align__(16) float BsT[64][33];

    int r0 = blockIdx.y * 64, o0 = blockIdx.x * 64;
    int tid = threadIdx.x;
    int tx = tid & 15, ty = tid >> 4;

    float acc[4][4] = {};

    for (int k0 = 0; k0 < CH; k0 += 32) {
#pragma unroll
        for (int s = 0; s < 8; s++) {
            int idx = tid + s * 256;
            int row = idx >> 5, col = idx & 31;
            As[row][col]  = g_ctx[(size_t)(r0 + row) * CH + k0 + col];
            BsT[row][col] = Wp[(size_t)(o0 + row) * CH + k0 + col];
        }
        __syncthreads();
#pragma unroll
        for (int cc = 0; cc < 32; cc++) {
            float aa[4], bb[4];
#pragma unroll
            for (int i = 0; i < 4; i++) aa[i] = As[ty * 4 + i][cc];
#pragma unroll
            for (int j = 0; j < 4; j++) bb[j] = BsT[tx * 4 + j][cc];
#pragma unroll
            for (int i = 0; i < 4; i++)
#pragma unroll
                for (int j = 0; j < 4; j++)
                    acc[i][j] = fmaf(aa[i], bb[j], acc[i][j]);
        }
        __syncthreads();
    }

#pragma unroll
    for (int i = 0; i < 4; i++) {
        int r = r0 + ty * 4 + i;
#pragma unroll
        for (int j = 0; j < 4; j++) {
            int o = o0 + tx * 4 + j;
            out[(size_t)r * CH + o] = acc[i][j] + bp[o];
        }
    }
}

// ============================================================
extern "C" void kernel_launch(void* const* d_in, const int* in_sizes, int n_in,
                              void* d_out, int out_size)
{
    const float* q    = (const float*)d_in[0];
    const float* k    = (const float*)d_in[1];
    const float* v    = (const float*)d_in[2];
    const float* Wq   = (const float*)d_in[3];
    const float* bq   = (const float*)d_in[4];
    const float* Wk   = (const float*)d_in[5];
    const float* bk   = (const float*)d_in[6];
    const float* Wv   = (const float*)d_in[7];
    const float* bv   = (const float*)d_in[8];
    const float* relw = (const float*)d_in[9];
    const float* relb = (const float*)d_in[10];
    const float* relv = (const float*)d_in[11];
    const float* Wp   = (const float*)d_in[12];
    const float* bp   = (const float*)d_in[13];
    (void)in_sizes; (void)n_in;

    float* out  = (float*)d_out;
    float* attn = (out_size >= OUT_ELEMS + ATTN_ELEMS) ? (out + OUT_ELEMS) : nullptr;

    static bool s_init = false;
    if (!s_init) {
        cudaFuncSetAttribute(attn_kernel,
                             cudaFuncAttributeMaxDynamicSharedMemorySize, SM_BYTES);
        s_init = true;
    }

    proj_kernel<<<dim3(25, 2, 6), 256>>>(q, k, v, Wq, bq, Wk, bk, Wv, bv);
    attn_kernel<<<dim3(HI, NHD, NB), 640, SM_BYTES>>>(relw, relb, relv, attn);
    outproj_kernel<<<dim3(4, 50), 256>>>(Wp, bp, out);
}

// round 8
// speedup vs baseline: 4.7772x; 1.0194x over previous
#include <cuda_runtime.h>
#include <math.h>

#define NB   2
#define NHD  8
#define HD   32
#define CH   256
#define HI   40
#define WIM  40
#define HW   1600
#define WSZ  15
#define WS2  225
#define NEGV 1e8f
#define INV_T 0.17677669529663687f   // 1/sqrt(32)

#define OUT_ELEMS  (HW*NB*CH)            // 819200
#define ATTN_ELEMS (NB*NHD*HW*WS2)       // 5760000

// ---- scratch ----
__device__ float g_qp[NB*NHD*HW*HD];
__device__ float g_kp[NB*NHD*HW*HD];   // scaled by 1/T
__device__ float g_vp[NB*NHD*HW*HD];
__device__ float g_ctx[HW*NB*CH];

// ============================================================
// Kernel 1: fused QKV projection (unchanged).
// ============================================================
__global__ void __launch_bounds__(256, 2) proj_kernel(
    const float* __restrict__ q, const float* __restrict__ k, const float* __restrict__ v,
    const float* __restrict__ Wq, const float* __restrict__ bq,
    const float* __restrict__ Wk, const float* __restrict__ bk,
    const float* __restrict__ Wv, const float* __restrict__ bv)
{
    __shared__ __align__(16) float Ws[128 * 33];
    __shared__ __align__(16) float Bs[32][64];

    int z = blockIdx.z;
    int n = z & 1, t = z >> 1;
    const float* X; const float* W; const float* b; float* Y; float scale;
    if (t == 0)      { X = q; W = Wq; b = bq; Y = g_qp; scale = 1.0f;  }
    else if (t == 1) { X = k; W = Wk; b = bk; Y = g_kp; scale = INV_T; }
    else             { X = v; W = Wv; b = bv; Y = g_vp; scale = 1.0f;  }
    X += (size_t)n * CH * HW;

    int o0 = blockIdx.y * 128, p0 = blockIdx.x * 64;
    int tid = threadIdx.x;
    int tx = tid & 15, ty = tid >> 4;

    float acc[8][4] = {};

    for (int k0 = 0; k0 < CH; k0 += 32) {
#pragma unroll
        for (int s = 0; s < 16; s++) {
            int idx = tid + s * 256;
            int row = idx >> 5, col = idx & 31;
            Ws[row * 33 + col] = W[(size_t)(o0 + row) * CH + k0 + col];
        }
#pragma unroll
        for (int s = 0; s < 8; s++) {
            int idx = tid + s * 256;
            int col = idx & 63, row = idx >> 6;
            Bs[row][col] = X[(size_t)(k0 + row) * HW + p0 + col];
        }
        __syncthreads();
#pragma unroll
        for (int cc = 0; cc < 32; cc++) {
            float4 b4 = *reinterpret_cast<const float4*>(&Bs[cc][tx * 4]);
            float bb[4] = {b4.x, b4.y, b4.z, b4.w};
            float aa[8];
#pragma unroll
            for (int i = 0; i < 8; i++) aa[i] = Ws[(ty * 8 + i) * 33 + cc];
#pragma unroll
            for (int i = 0; i < 8; i++)
#pragma unroll
                for (int j = 0; j < 4; j++)
                    acc[i][j] = fmaf(aa[i], bb[j], acc[i][j]);
        }
        __syncthreads();
    }

#pragma unroll
    for (int i = 0; i < 8; i++) {
        int o = o0 + ty * 8 + i;
        int h = o >> 5, d = o & 31;
        float bias = b[o];
#pragma unroll
        for (int j = 0; j < 4; j++) {
            int p = p0 + tx * 4 + j;
            float val = (acc[i][j] + bias) * scale;
            Y[((size_t)(n * NHD + h) * HW + p) * HD + d] = val;
        }
    }
}

// ============================================================
// Kernel 2: local attention v5. Block per (qy PAIR, h, n). 640 thr.
//   K: 16 rows x PADW(54) x pitch 36 (float4 conflict-free), pads zeroed.
//   L: 80 queries x pitch 228 (16B-aligned rows for broadcast float4).
//   V: 16 rows x 54 x pitch 32 (reuses K region).
//   relw [w][d] pitch 36; relv [d][w] pitch 228 (float4 lane-stride 16B).
// ============================================================
#define GQ    2
#define QG    80            // queries per block
#define KROWS 16            // GQ + 14
#define PADW  54
#define KP    36
#define LP    228
#define SM_K      0                          // 16*54*36 = 31104
#define SM_L      31104                      // 80*228   = 18240
#define SM_R      49344                      // relw 8100 / relv 7296
#define SM_B      57444                      // 228
#define SM_FLOATS 57672
#define SM_BYTES  (SM_FLOATS * 4)            // 230688 B

__global__ void __launch_bounds__(640, 1) attn_kernel(
    const float* __restrict__ relw_g,   // [NHD][WS2][HD]
    const float* __restrict__ relb_g,   // [NHD][WS2]
    const float* __restrict__ relv_g,   // [NHD][HD][WS2]
    float* __restrict__ attn_out)       // may be null
{
    int qy0 = blockIdx.x * GQ, h = blockIdx.y, n = blockIdx.z;
    int tid = threadIdx.x;
    extern __shared__ __align__(16) float sm[];
    float* sK = sm + SM_K;
    float* sL = sm + SM_L;
    float* sR = sm + SM_R;
    float* sB = sm + SM_B;

    int nh_base = (n * NHD + h) * HW;
    const float4 z4 = make_float4(0.f, 0.f, 0.f, 0.f);

    // ---- stage K (16 rows, OOB rows -> 0), pad cols, relw, relb ----
    for (int i = tid; i < KROWS * 320; i += 640) {
        int r = i / 320, rem = i - r * 320;
        int ky = qy0 - 7 + r;
        float4 val = z4;
        if ((unsigned)ky < HI)
            val = reinterpret_cast<const float4*>(
                      g_kp + (size_t)(nh_base + ky * WIM) * HD)[rem];
        int kx = rem >> 3, u = rem & 7;
        *reinterpret_cast<float4*>(sK + (r * PADW + 7 + kx) * KP + 4 * u) = val;
    }
    for (int i = tid; i < KROWS * 112; i += 640) {
        int r = i / 112, rem = i - r * 112;
        int c = rem >> 3, u = rem & 7;
        int col = (c < 7) ? c : (c + 40);             // pads: 0..6, 47..53
        *reinterpret_cast<float4*>(sK + (r * PADW + col) * KP + 4 * u) = z4;
    }
    {   // relw [w][d] -> pitch 36
        const float* src = relw_g + (size_t)h * WS2 * HD;
        for (int i = tid; i < WS2 * HD; i += 640) {
            int w = i >> 5, d = i & 31;
            sR[w * KP + d] = src[i];
        }
    }
    {
        const float* src = relb_g + (size_t)h * WS2;
        for (int i = tid; i < WS2; i += 640) sB[i] = src[i];
    }
    __syncthreads();

    // ---- logits: thread = (qg = tid%80, wg = tid/80 in 0..7) ----
    {
        int qg = tid % QG;
        int wg = tid / QG;
        int qyl = (qg >= 40) ? 1 : 0;
        int qx = qg - qyl * 40;
        float4 qv[8];
        {
            const float4* qsrc = reinterpret_cast<const float4*>(
                g_qp + (size_t)(nh_base + (qy0 + qyl) * WIM + qx) * HD);
#pragma unroll
            for (int u = 0; u < 8; u++) qv[u] = qsrc[u];
        }
#pragma unroll 1
        for (int w = wg; w < WS2; w += 8) {
            int wy = w / WSZ, wx = w - wy * WSZ;
            int ky = qy0 + qyl + wy - 7, kx = qx + wx - 7;
            bool img = ((unsigned)ky < HI) & ((unsigned)kx < WIM);
            const float4* k4 = reinterpret_cast<const float4*>(
                sK + ((qyl + wy) * PADW + qx + wx) * KP);
            const float4* r4 = reinterpret_cast<const float4*>(sR + w * KP);
            float4 aqk = z4, arl = z4;
#pragma unroll
            for (int u = 0; u < 8; u++) {
                float4 kv = k4[u], rv = r4[u], qq = qv[u];
                aqk.x = fmaf(qq.x, kv.x, aqk.x);
                aqk.y = fmaf(qq.y, kv.y, aqk.y);
                aqk.z = fmaf(qq.z, kv.z, aqk.z);
                aqk.w = fmaf(qq.w, kv.w, aqk.w);
                arl.x = fmaf(qq.x, rv.x, arl.x);
                arl.y = fmaf(qq.y, rv.y, arl.y);
                arl.z = fmaf(qq.z, rv.z, arl.z);
                arl.w = fmaf(qq.w, rv.w, arl.w);
            }
            float qk = (aqk.x + aqk.y) + (aqk.z + aqk.w);
            float rl = (arl.x + arl.y) + (arl.z + arl.w);
            sL[qg * LP + w] = (img ? qk : -NEGV) + rl + sB[w];
        }
    }
    __syncthreads();

    // ---- V + relv staging (disjoint from softmax's sL) ----
    for (int i = tid; i < KROWS * 320; i += 640) {
        int r = i / 320, rem = i - r * 320;
        int ky = qy0 - 7 + r;
        float4 val = z4;
        if ((unsigned)ky < HI)
            val = reinterpret_cast<const float4*>(
                      g_vp + (size_t)(nh_base + ky * WIM) * HD)[rem];
        reinterpret_cast<float4*>(sK + (r * PADW + 7) * HD)[rem] = val;
    }
    for (int i = tid; i < KROWS * 112; i += 640) {    // V pad cols (pitch 32)
        int r = i / 112, rem = i - r * 112;
        int c = rem >> 3, u = rem & 7;
        int col = (c < 7) ? c : (c + 40);
        *reinterpret_cast<float4*>(sK + (r * PADW + col) * HD + 4 * u) = z4;
    }
    {   // relv [d][w] -> pitch 228
        const float* src = relv_g + (size_t)h * HD * WS2;
        for (int i = tid; i < HD * WS2; i += 640) {
            int d = i / WS2, w = i - d * WS2;
            sR[d * LP + w] = src[i];
        }
    }

    // ---- softmax: 20 warps x 4 queries (reads/writes sL only) ----
    {
        int warp = tid >> 5, lane = tid & 31;
#pragma unroll 1
        for (int qq = 0; qq < 4; qq++) {
            int qg = warp * 4 + qq;
            float* Lp = sL + qg * LP;
            float vals[8];
            float m = -3.0e38f;
#pragma unroll
            for (int u = 0; u < 8; u++) {
                int w = lane + u * 32;
                vals[u] = (w < WS2) ? Lp[w] : -3.0e38f;
                m = fmaxf(m, vals[u]);
            }
#pragma unroll
            for (int off = 16; off > 0; off >>= 1)
                m = fmaxf(m, __shfl_xor_sync(0xffffffffu, m, off));
            float s = 0.0f;
#pragma unroll
            for (int u = 0; u < 8; u++) { float p = __expf(vals[u] - m); vals[u] = p; s += p; }
#pragma unroll
            for (int off = 16; off > 0; off >>= 1)
                s += __shfl_xor_sync(0xffffffffu, s, off);
            float inv = 1.0f / s;
            int qyl = (qg >= 40) ? 1 : 0;
            int qx = qg - qyl * 40;
            float* gp = attn_out
                ? attn_out + (size_t)(nh_base + (qy0 + qyl) * WIM + qx) * WS2
                : nullptr;
#pragma unroll
            for (int u = 0; u < 8; u++) {
                int w = lane + u * 32;
                if (w < WS2) {
                    float p = vals[u] * inv;
                    Lp[w] = p;
                    if (gp) gp[w] = p;
                }
            }
        }
    }
    __syncthreads();

    // ---- aggregation: warp = 4 consecutive queries (same row), lane = d ----
    {
        int warp = tid >> 5, lane = tid & 31;
        int q0 = warp * 4;                 // 40%4==0 -> no row straddle
        int qyl = (q0 >= 40) ? 1 : 0;
        int qx0 = q0 - qyl * 40;
        float av[4] = {0.f, 0.f, 0.f, 0.f};
        float ab[4] = {0.f, 0.f, 0.f, 0.f};
        int wy = 0, wx = 0;                // tracks w4 = g*4, uniform per warp
#pragma unroll 1
        for (int g = 0; g < 56; g++) {     // w = 0..223
            int w4 = g * 4;
            float4 rv4 = *reinterpret_cast<const float4*>(sR + lane * LP + w4);
            float rls[4] = {rv4.x, rv4.y, rv4.z, rv4.w};
            // element coords for w4..w4+3 (wx may wrap once within group)
#pragma unroll
            for (int j = 0; j < 4; j++) {
                float4 p4 = *reinterpret_cast<const float4*>(sL + (q0 + j) * LP + w4);
                float ps[4] = {p4.x, p4.y, p4.z, p4.w};
#pragma unroll
                for (int t = 0; t < 4; t++) {
                    int wx_t = wx + t, wy_t = wy;
                    if (wx_t >= WSZ) { wx_t -= WSZ; wy_t++; }
                    const float* vb = sK + ((qyl + wy_t) * PADW + qx0 + j + wx_t) * HD + lane;
                    av[j] = fmaf(ps[t], *vb, av[j]);
                    ab[j] = fmaf(ps[t], rls[t], ab[j]);
                }
            }
            wx += 4;
            if (wx >= WSZ) { wx -= WSZ; wy++; }
        }
        {   // tail w = 224 (wy=14, wx=14)
            float rl = sR[lane * LP + 224];
#pragma unroll
            for (int j = 0; j < 4; j++) {
                float p = sL[(q0 + j) * LP + 224];
                const float* vb = sK + ((qyl + 14) * PADW + qx0 + j + 14) * HD + lane;
                av[j] = fmaf(p, *vb, av[j]);
                ab[j] = fmaf(p, rl, ab[j]);
            }
        }
#pragma unroll
        for (int j = 0; j < 4; j++) {
            int qx = qx0 + j;
            int iy = (qy0 + qyl) * WIM + qx;
            g_ctx[((size_t)iy * NB + n) * CH + h * HD + lane] = av[j] + ab[j];
        }
    }
}

// ============================================================
// Kernel 3: output projection (unchanged).
// ============================================================
__global__ void __launch_bounds__(256) outproj_kernel(
    const float* __restrict__ Wp, const float* __restrict__ bp,
    float* __restrict__ out)
{
    __shared__ __align__(16) float As[64][32];
    __shared__ __align__(16) float BsT[64][33];

    int r0 = blockIdx.y * 64, o0 = blockIdx.x * 64;
    int tid = threadIdx.x;
    int tx = tid & 15, ty = tid >> 4;

    float acc[4][4] = {};

    for (int k0 = 0; k0 < CH; k0 += 32) {
#pragma unroll
        for (int s = 0; s < 8; s++) {
            int idx = tid + s * 256;
            int row = idx >> 5, col = idx & 31;
            As[row][col]  = g_ctx[(size_t)(r0 + row) * CH + k0 + col];
            BsT[row][col] = Wp[(size_t)(o0 + row) * CH + k0 + col];
        }
        __syncthreads();
#pragma unroll
        for (int cc = 0; cc < 32; cc++) {
            float aa[4], bb[4];
#pragma unroll
            for (int i = 0; i < 4; i++) aa[i] = As[ty * 4 + i][cc];
#pragma unroll
            for (int j = 0; j < 4; j++) bb[j] = BsT[tx * 4 + j][cc];
#pragma unroll
            for (int i = 0; i < 4; i++)
#pragma unroll
                for (int j = 0; j < 4; j++)
                    acc[i][j] = fmaf(aa[i], bb[j], acc[i][j]);
        }
        __syncthreads();
    }

#pragma unroll
    for (int i = 0; i < 4; i++) {
        int r = r0 + ty * 4 + i;
#pragma unroll
        for (int j = 0; j < 4; j++) {
            int o = o0 + tx * 4 + j;
            out[(size_t)r * CH + o] = acc[i][j] + bp[o];
        }
    }
}

// ============================================================
extern "C" void kernel_launch(void* const* d_in, const int* in_sizes, int n_in,
                              void* d_out, int out_size)
{
    const float* q    = (const float*)d_in[0];
    const float* k    = (const float*)d_in[1];
    const float* v    = (const float*)d_in[2];
    const float* Wq   = (const float*)d_in[3];
    const float* bq   = (const float*)d_in[4];
    const float* Wk   = (const float*)d_in[5];
    const float* bk   = (const float*)d_in[6];
    const float* Wv   = (const float*)d_in[7];
    const float* bv   = (const float*)d_in[8];
    const float* relw = (const float*)d_in[9];
    const float* relb = (const float*)d_in[10];
    const float* relv = (const float*)d_in[11];
    const float* Wp   = (const float*)d_in[12];
    const float* bp   = (const float*)d_in[13];
    (void)in_sizes; (void)n_in;

    float* out  = (float*)d_out;
    float* attn = (out_size >= OUT_ELEMS + ATTN_ELEMS) ? (out + OUT_ELEMS) : nullptr;

    static bool s_init = false;
    if (!s_init) {
        cudaFuncSetAttribute(attn_kernel,
                             cudaFuncAttributeMaxDynamicSharedMemorySize, SM_BYTES);
        s_init = true;
    }

    proj_kernel<<<dim3(25, 2, 6), 256>>>(q, k, v, Wq, bq, Wk, bk, Wv, bv);
    attn_kernel<<<dim3(HI / GQ, NHD, NB), 640, SM_BYTES>>>(relw, relb, relv, attn);
    outproj_kernel<<<dim3(4, 50), 256>>>(Wp, bp, out);
}